// round 2
// baseline (speedup 1.0000x reference)
#include <cuda_runtime.h>
#include <cuda_bf16.h>
#include <math.h>

#define HH 1024
#define NN 64
#define LL 1024
#define NG 8          // states per thread
#define LT 32         // number of l-chunk threads
#define CHUNK (LL/LT) // 32 l-values per thread
#define THREADS (LT*NG)

__global__ __launch_bounds__(THREADS)
void ssk_diag_kernel(const float* __restrict__ log_dt,
                     const float* __restrict__ Lre,
                     const float* __restrict__ Lim,
                     const float* __restrict__ Bm,
                     const float* __restrict__ Cre,
                     const float* __restrict__ Cim,
                     const float* __restrict__ Dm,
                     float* __restrict__ out) {
    const int h = blockIdx.x;
    __shared__ float s_wre[NN], s_wim[NN];       // w = exp(dtA)
    __shared__ float s_cre[NN], s_cim[NN];       // 2*C*B_bar
    __shared__ float s_pre[5][NN], s_pim[5][NN]; // w^{32*2^k}, k=0..4
    __shared__ float s_K[LL];

    const int tid = threadIdx.x;

    // ---- setup: per-state parameters (64 threads) ----
    if (tid < NN) {
        const int idx = h * NN + tid;
        float dt  = expf(log_dt[h]);
        float lre = Lre[idx];
        float lim = Lim[idx];
        float are = dt * lre;
        float aim = dt * lim;
        float er  = expf(are);
        float s, c;
        sincosf(aim, &s, &c);            // NOTE: sin first, cos second
        float wre = er * c;
        float wim = er * s;
        // expm1(dtA): Re = expm1(are)*cos(aim) - 2*sin^2(aim/2), Im = e^are*sin(aim)
        float em   = expm1f(are);
        float sh   = sinf(0.5f * aim);
        float emre = fmaf(em, c, -2.0f * sh * sh);
        float emim = er * s;
        // B_bar = expm1(dtA)/Lambda * B   (complex divide by Lambda)
        float inv  = 1.0f / fmaf(lre, lre, lim * lim);
        float bre  = (emre * lre + emim * lim) * inv;
        float bim  = (emim * lre - emre * lim) * inv;
        float b    = Bm[idx];
        bre *= b;  bim *= b;
        // CB = C * B_bar, fold in the factor 2 from 2*Re(K)
        float cr = Cre[idx], ci = Cim[idx];
        float cbre = 2.0f * (cr * bre - ci * bim);
        float cbim = 2.0f * (cr * bim + ci * bre);
        s_wre[tid] = wre;  s_wim[tid] = wim;
        s_cre[tid] = cbre; s_cim[tid] = cbim;
        // power ladder: w^2, w^4, ..., w^32 (5 squarings), then store
        // w^{32*2^k} for k=0..4 (w^32 .. w^512)
        float pr = wre, pi = wim;
        #pragma unroll
        for (int k = 0; k < 5; k++) {
            float nr = fmaf(pr, pr, -pi * pi);
            float ni = 2.0f * pr * pi;
            pr = nr; pi = ni;
        }
        #pragma unroll
        for (int k = 0; k < 5; k++) {
            s_pre[k][tid] = pr;
            s_pim[k][tid] = pi;
            float nr = fmaf(pr, pr, -pi * pi);
            float ni = 2.0f * pr * pi;
            pr = nr; pi = ni;
        }
    }
    __syncthreads();

    // ---- main: geometric recurrence ----
    const int g  = tid & (NG - 1);   // state group (== lane & 7)
    const int t  = tid >> 3;         // l-chunk index (0..31)
    const int l0 = t * CHUNK;

    float wre[NG], wim[NG], cre[NG], cim[NG], zre[NG], zim[NG];
    #pragma unroll
    for (int j = 0; j < NG; j++) {
        const int n = g * NG + j;
        wre[j] = s_wre[n]; wim[j] = s_wim[n];
        cre[j] = s_cre[n]; cim[j] = s_cim[n];
        // z = w^{l0} = product of w^{32*2^k} over set bits of t (exact small-arg math)
        float zr = 1.0f, zi = 0.0f;
        #pragma unroll
        for (int k = 0; k < 5; k++) {
            if (t & (1 << k)) {
                float pr = s_pre[k][n], pi = s_pim[k][n];
                float nr = fmaf(zr, pr, -zi * pi);
                float ni = fmaf(zr, pi,  zi * pr);
                zr = nr; zi = ni;
            }
        }
        zre[j] = zr; zim[j] = zi;
    }

    const float Dh = Dm[h];
    #pragma unroll 4
    for (int i = 0; i < CHUNK; i++) {
        float acc = 0.0f;
        #pragma unroll
        for (int j = 0; j < NG; j++) {
            acc = fmaf(cre[j], zre[j], acc);
            acc = fmaf(-cim[j], zim[j], acc);
            float nr = fmaf(zre[j], wre[j], -zim[j] * wim[j]);
            float ni = fmaf(zre[j], wim[j],  zim[j] * wre[j]);
            zre[j] = nr;
            zim[j] = ni;
        }
        // reduce across the 8 state groups (lanes differing in bits 0..2)
        acc += __shfl_xor_sync(0xffffffffu, acc, 1);
        acc += __shfl_xor_sync(0xffffffffu, acc, 2);
        acc += __shfl_xor_sync(0xffffffffu, acc, 4);
        if (g == 0) {
            const int l = l0 + i;
            float v = acc;
            if (l == 0) v += Dh;
            s_K[l] = v;
        }
    }
    __syncthreads();

    // ---- coalesced writeout: 256 threads x float4 = 1024 floats ----
    float4* o4 = reinterpret_cast<float4*>(out + (size_t)h * LL);
    const float4* k4 = reinterpret_cast<const float4*>(s_K);
    o4[tid] = k4[tid];
}

extern "C" void kernel_launch(void* const* d_in, const int* in_sizes, int n_in,
                              void* d_out, int out_size) {
    const float* log_dt = (const float*)d_in[0];
    const float* Lre    = (const float*)d_in[1];
    const float* Lim    = (const float*)d_in[2];
    const float* Bm     = (const float*)d_in[3];
    const float* Cre    = (const float*)d_in[4];
    const float* Cim    = (const float*)d_in[5];
    const float* Dm     = (const float*)d_in[6];
    float* out = (float*)d_out;
    ssk_diag_kernel<<<HH, THREADS>>>(log_dt, Lre, Lim, Bm, Cre, Cim, Dm, out);
}

// round 3
// speedup vs baseline: 1.2896x; 1.2896x over previous
#include <cuda_runtime.h>
#include <cuda_bf16.h>
#include <math.h>

#define HH 1024
#define NN 64
#define LL 1024
#define NG 8          // states per thread
#define LT 32         // number of l-chunk threads
#define CHUNK (LL/LT) // 32 l-values per thread
#define THREADS (LT*NG)
#define NP (NG/2)     // packed f32x2 pairs per thread

typedef unsigned long long u64;

__device__ __forceinline__ u64 pack2(float lo, float hi) {
    u64 r; asm("mov.b64 %0, {%1, %2};" : "=l"(r) : "f"(lo), "f"(hi)); return r;
}
__device__ __forceinline__ void unpack2(u64 v, float& lo, float& hi) {
    asm("mov.b64 {%0, %1}, %2;" : "=f"(lo), "=f"(hi) : "l"(v));
}
__device__ __forceinline__ u64 mul2(u64 a, u64 b) {
    u64 r; asm("mul.rn.f32x2 %0, %1, %2;" : "=l"(r) : "l"(a), "l"(b)); return r;
}
__device__ __forceinline__ u64 fma2(u64 a, u64 b, u64 c) {
    u64 r; asm("fma.rn.f32x2 %0, %1, %2, %3;" : "=l"(r) : "l"(a), "l"(b), "l"(c)); return r;
}
__device__ __forceinline__ u64 add2(u64 a, u64 b) {
    u64 r; asm("add.rn.f32x2 %0, %1, %2;" : "=l"(r) : "l"(a), "l"(b)); return r;
}

__global__ __launch_bounds__(THREADS)
void ssk_diag_kernel(const float* __restrict__ log_dt,
                     const float* __restrict__ Lre,
                     const float* __restrict__ Lim,
                     const float* __restrict__ Bm,
                     const float* __restrict__ Cre,
                     const float* __restrict__ Cim,
                     const float* __restrict__ Dm,
                     float* __restrict__ out) {
    const int h = blockIdx.x;
    __shared__ float s_wre[NN], s_wim[NN];       // w = exp(dtA)
    __shared__ float s_cre[NN], s_cim[NN];       // 2*C*B_bar
    __shared__ float s_a[NN],   s_bn[NN];        // 2*Re(w), -|w|^2
    __shared__ float s_pre[5][NN], s_pim[5][NN]; // w^{32*2^k}, k=0..4
    __shared__ float s_K[LL];

    const int tid = threadIdx.x;

    // ---- setup: per-state parameters (64 threads) ----
    if (tid < NN) {
        const int idx = h * NN + tid;
        float dt  = expf(log_dt[h]);
        float lre = Lre[idx];
        float lim = Lim[idx];
        float are = dt * lre;
        float aim = dt * lim;
        float er  = expf(are);
        float s, c;
        sincosf(aim, &s, &c);            // sin first, cos second
        float wre = er * c;
        float wim = er * s;
        // expm1(dtA): Re = expm1(are)*cos(aim) - 2*sin^2(aim/2), Im = e^are*sin(aim)
        float em   = expm1f(are);
        float sh   = sinf(0.5f * aim);
        float emre = fmaf(em, c, -2.0f * sh * sh);
        float emim = er * s;
        // B_bar = expm1(dtA)/Lambda * B   (complex divide by Lambda)
        float inv  = 1.0f / fmaf(lre, lre, lim * lim);
        float bre  = (emre * lre + emim * lim) * inv;
        float bim  = (emim * lre - emre * lim) * inv;
        float b    = Bm[idx];
        bre *= b;  bim *= b;
        // CB = C * B_bar, fold in the factor 2 from 2*Re(K)
        float cr = Cre[idx], ci = Cim[idx];
        float cbre = 2.0f * (cr * bre - ci * bim);
        float cbim = 2.0f * (cr * bim + ci * bre);
        s_wre[tid] = wre;  s_wim[tid] = wim;
        s_cre[tid] = cbre; s_cim[tid] = cbim;
        s_a[tid]   = 2.0f * wre;
        s_bn[tid]  = -fmaf(wre, wre, wim * wim);
        // power ladder: 5 squarings to w^32, then store w^{32*2^k}, k=0..4
        float pr = wre, pi = wim;
        #pragma unroll
        for (int k = 0; k < 5; k++) {
            float nr = fmaf(pr, pr, -pi * pi);
            float ni = 2.0f * pr * pi;
            pr = nr; pi = ni;
        }
        #pragma unroll
        for (int k = 0; k < 5; k++) {
            s_pre[k][tid] = pr;
            s_pim[k][tid] = pi;
            float nr = fmaf(pr, pr, -pi * pi);
            float ni = 2.0f * pr * pi;
            pr = nr; pi = ni;
        }
    }
    __syncthreads();

    // ---- main: packed second-order real recurrence ----
    const int g  = tid & (NG - 1);   // state group (== lane & 7)
    const int t  = tid >> 3;         // l-chunk index (0..31)
    const int l0 = t * CHUNK;

    float x0[NG], x1[NG], av[NG], bv[NG];
    #pragma unroll
    for (int j = 0; j < NG; j++) {
        const int n = g * NG + j;
        const float wre = s_wre[n], wim = s_wim[n];
        const float cbre = s_cre[n], cbim = s_cim[n];
        av[j] = s_a[n];
        bv[j] = s_bn[n];
        // z = w^{l0} via binary ladder over set bits of t
        float zr = 1.0f, zi = 0.0f;
        #pragma unroll
        for (int k = 0; k < 5; k++) {
            if (t & (1 << k)) {
                float pr = s_pre[k][n], pi = s_pim[k][n];
                float nr = fmaf(zr, pr, -zi * pi);
                float ni = fmaf(zr, pi,  zi * pr);
                zr = nr; zi = ni;
            }
        }
        x0[j] = fmaf(cbre, zr, -cbim * zi);          // Re(cb * w^l0)
        float z1r = fmaf(zr, wre, -zi * wim);
        float z1i = fmaf(zr, wim,  zi * wre);
        x1[j] = fmaf(cbre, z1r, -cbim * z1i);        // Re(cb * w^(l0+1))
    }

    u64 P[NP], Q[NP], A2[NP], BN[NP];
    #pragma unroll
    for (int k = 0; k < NP; k++) {
        P[k]  = pack2(x0[2*k], x0[2*k+1]);
        Q[k]  = pack2(x1[2*k], x1[2*k+1]);
        A2[k] = pack2(av[2*k], av[2*k+1]);
        BN[k] = pack2(bv[2*k], bv[2*k+1]);
    }

    const float Dh = Dm[h];
    #pragma unroll
    for (int i = 0; i < CHUNK; i++) {
        // emit sum over this thread's 8 states at l = l0 + i (values in P)
        u64 s01 = add2(P[0], P[1]);
        u64 s23 = add2(P[2], P[3]);
        u64 sp  = add2(s01, s23);
        float lo, hi;
        unpack2(sp, lo, hi);
        float acc = lo + hi;
        acc += __shfl_xor_sync(0xffffffffu, acc, 1);
        acc += __shfl_xor_sync(0xffffffffu, acc, 2);
        acc += __shfl_xor_sync(0xffffffffu, acc, 4);
        if (g == 0) {
            float v = acc;
            if (i == 0 && t == 0) v += Dh;
            s_K[l0 + i] = v;
        }
        // advance: x_{l+2} = a*x_{l+1} + bn*x_l
        #pragma unroll
        for (int k = 0; k < NP; k++) {
            u64 tt = mul2(BN[k], P[k]);
            u64 r  = fma2(A2[k], Q[k], tt);
            P[k] = Q[k];
            Q[k] = r;
        }
    }
    __syncthreads();

    // ---- coalesced writeout: 256 threads x float4 = 1024 floats ----
    float4* o4 = reinterpret_cast<float4*>(out + (size_t)h * LL);
    const float4* k4 = reinterpret_cast<const float4*>(s_K);
    o4[tid] = k4[tid];
}

extern "C" void kernel_launch(void* const* d_in, const int* in_sizes, int n_in,
                              void* d_out, int out_size) {
    const float* log_dt = (const float*)d_in[0];
    const float* Lre    = (const float*)d_in[1];
    const float* Lim    = (const float*)d_in[2];
    const float* Bm     = (const float*)d_in[3];
    const float* Cre    = (const float*)d_in[4];
    const float* Cim    = (const float*)d_in[5];
    const float* Dm     = (const float*)d_in[6];
    float* out = (float*)d_out;
    ssk_diag_kernel<<<HH, THREADS>>>(log_dt, Lre, Lim, Bm, Cre, Cim, Dm, out);
}